// round 14
// baseline (speedup 1.0000x reference)
#include <cuda_runtime.h>
#include <cstdint>

#define GRID1   20
#define NCPAD   8192
#define CAP     16             // bucket capacity (overflow P ~ 2e-12)
#define KC      20             // merged candidate cap (P(cnt>20) ~ 1e-9)
#define KC_L    12             // per-group-thread local cap
#define STAGE   24             // per-row smem staging slots
#define CSTRIDE 32
#define MAXM    8192
#define MAXN    8192
#define GBLK    128
#define TBLK    512
#define GSZ     8              // threads per pred row
#define ROWS_PB (TBLK / GSZ)   // 64 rows per block
#define OWNER_INIT 0x7FFFFFFF

typedef unsigned long long u64;

// ---------------- device scratch (no allocations allowed) ----------------
__device__ int            g_cellcnt[NCPAD];          // zero-init; phase D re-zeros
__device__ float4         g_bucket[NCPAD * CAP];     // (x,y,z,bitcast id)
__device__ uint4          g_row[MAXM];               // cnt | first 7 sorted candidates
__device__ unsigned short g_sorted[MAXM * CSTRIDE];  // overflow (pos >= 7)
__device__ int            g_owner[MAXN];             // packed (row<<5 | pos)
__device__ float          g_acc[5];
__device__ volatile unsigned g_bcnt[4];              // zero-init; self-resetting
__device__ volatile unsigned g_bgen[4];              // monotonic generation

__device__ __forceinline__ int cell1(float x) {
    int c = (int)floorf(x * 0.2f);
    return min(max(c, 0), GRID1 - 1);
}

// Generation-based grid barrier; all GBLK blocks co-resident (128 <= 148 SMs).
__device__ __forceinline__ void gsync(int k) {
    __syncthreads();
    if (threadIdx.x == 0) {
        unsigned old = g_bgen[k];
        __threadfence();
        unsigned a = atomicAdd((unsigned*)&g_bcnt[k], 1u);
        if (a == GBLK - 1) {
            g_bcnt[k] = 0;
            __threadfence();
            atomicAdd((unsigned*)&g_bgen[k], 1u);
        } else {
            while (g_bgen[k] == old) { }
        }
    }
    __syncthreads();
    __threadfence();
}

// candidate p of a row given its packed uint4; own=true may use L1 (own writes)
__device__ __forceinline__ int cand_at(uint4 rv, int p, int row, bool own) {
    if (p < 7) {
        unsigned w = (p == 0) ? rv.x : (p < 3) ? rv.y : (p < 5) ? rv.z : rv.w;
        int sh = (p == 0) ? 16 : ((p & 1) ? 0 : 16);
        return (int)((w >> sh) & 0xFFFFu);
    }
    const unsigned short* q = &g_sorted[(size_t)row * CSTRIDE + p];
    return own ? (int)*q : (int)__ldcg(q);
}

__device__ __forceinline__ float sl1(float x) {
    float a = fabsf(x);
    return (a < 1.0f) ? 0.5f * a * a : a - 0.5f;
}

__global__ void __launch_bounds__(TBLK)
fused_kernel(const float* __restrict__ pred, const float* __restrict__ gt,
             int m, int n, float* __restrict__ out) {
    __shared__ u64 s_keys[ROWS_PB * STAGE];     // 12 KB staging
    __shared__ int s_cnt[ROWS_PB];
    int b = blockIdx.x, tid = threadIdx.x;
    int lane = tid & 31;
    int gtid = b * TBLK + tid;
    int row  = gtid >> 3;                        // octet: 8 threads per pred row
    int sub  = tid & (GSZ - 1);
    int lrow = tid >> 3;                         // row index within block
    bool rowv = (row < m);
    bool lead = (sub == 0) && rowv;

    if (tid < ROWS_PB) s_cnt[tid] = 0;

    // All octet lanes load their row's pred xyz (same line; broadcast).
    float px = 0.f, py = 0.f, pz = 0.f;
    if (rowv) {
        px = __ldg(&pred[row * 7 + 0]);
        py = __ldg(&pred[row * 7 + 1]);
        pz = __ldg(&pred[row * 7 + 2]);
    }

    // ========== phase A: build + init, spread over ALL blocks ==============
    // Each block owns 64 gt rows: r = b*64 + tid (tid < 64).
    if (b == 0 && tid >= ROWS_PB && tid < ROWS_PB + 5) g_acc[tid - ROWS_PB] = 0.0f;
    if (tid < ROWS_PB) {
        int r = b * ROWS_PB + tid;
        if (r < n) {
            g_owner[r] = OWNER_INIT;
            const float* g = gt + (size_t)r * 7;
            float gx = __ldg(g), gy = __ldg(g + 1), gz = __ldg(g + 2);
            int c = (cell1(gz) * GRID1 + cell1(gy)) * GRID1 + cell1(gx);
            int slot = atomicAdd(&g_cellcnt[c], 1);
            if (slot < CAP)
                g_bucket[c * CAP + slot] =
                    make_float4(gx, gy, gz, __int_as_float(r));
        }
    }
    gsync(0);

    // ========== phase B: octet-parallel query ================================
    // 27 neighbor cells split over 8 threads (k = sub + 8t, k<27): exact
    // partition, union == full [cell1(px-5),cell1(px+5)]^3 superset (monotone
    // f32 ops); exact dsq<25 test -> identical candidate set to brute force
    // (rounds 1-13). Each thread min-sweeps hits into a sorted local list,
    // stages to SMEM; the leader merges via the same min-sweep. Keys
    // (fbits(dsq)<<32 | j) unique -> staging-order races erased by the sort,
    // deterministic exact serial-argmin order.
    uint4 rv = make_uint4(0, 0, 0, 0);
    int   cnt = 0;
    if (rowv) {
        int x0 = cell1(px - 5.0f), x1 = cell1(px + 5.0f);
        int y0 = cell1(py - 5.0f), y1 = cell1(py + 5.0f);
        int z0 = cell1(pz - 5.0f), z1 = cell1(pz + 5.0f);

        u64 loc[KC_L];
        #pragma unroll
        for (int k = 0; k < KC_L; ++k) loc[k] = ~0ull;
        int lc = 0;

        int    cc[4], ci[4];
        float4 v0[4];
        #pragma unroll
        for (int t = 0; t < 4; ++t) {
            int k = sub + GSZ * t;
            int zz = z0 + k / 9, yy = y0 + (k % 9) / 3, xx = x0 + k % 3;
            bool ok = (k < 27) && (zz <= z1) && (yy <= y1) && (xx <= x1);
            int c = (zz * GRID1 + yy) * GRID1 + xx;
            c = min(max(c, 0), NCPAD - 1);       // clamp: always in-bounds
            ci[t] = c;
            cc[t] = ok ? __ldg(&g_cellcnt[c]) : 0;
        }
        #pragma unroll
        for (int t = 0; t < 4; ++t) v0[t] = __ldg(&g_bucket[ci[t] * CAP]);

        #pragma unroll
        for (int t = 0; t < 4; ++t) {
            int c2 = min(cc[t], CAP);
            for (int e = 0; e < c2; ++e) {       // c2>1 rare (mean ~1)
                float4 v = (e == 0) ? v0[t] : __ldg(&g_bucket[ci[t] * CAP + e]);
                float dx = px - v.x, dy = py - v.y, dz = pz - v.z;
                float d = fmaf(dx, dx, fmaf(dy, dy, dz * dz));
                if (d < 25.0f) {
                    u64 key = ((u64)__float_as_uint(d) << 32)
                            | (unsigned)__float_as_int(v.w);
                    ++lc;
                    #pragma unroll
                    for (int k2 = 0; k2 < KC_L; ++k2) {   // register min-sweep
                        u64 mn = min(loc[k2], key);
                        key = loc[k2] ^ key ^ mn;
                        loc[k2] = mn;
                    }
                }
            }
        }
        lc = min(lc, KC_L);
        if (lc > 0) {
            int pos = atomicAdd(&s_cnt[lrow], lc);
            #pragma unroll
            for (int e = 0; e < KC_L; ++e)
                if (e < lc && pos + e < STAGE)
                    s_keys[lrow * STAGE + pos + e] = loc[e];
        }
    }
    __syncwarp(0xFFFFFFFFu);                     // octet is intra-warp

    if (lead) {
        int tot = min(s_cnt[lrow], STAGE);
        u64 a[KC];
        #pragma unroll
        for (int k = 0; k < KC; ++k) a[k] = ~0ull;
        for (int e = 0; e < tot; ++e) {
            u64 key = s_keys[lrow * STAGE + e];
            #pragma unroll
            for (int k2 = 0; k2 < KC; ++k2) {    // merge min-sweep
                u64 mn = min(a[k2], key);
                key = a[k2] ^ key ^ mn;
                a[k2] = mn;
            }
        }
        cnt = min(tot, KC);
        unsigned c7[7];
        #pragma unroll
        for (int k = 0; k < 7; ++k)
            c7[k] = (k < cnt) ? (unsigned)(a[k] & 0xFFFFu) : 0u;
        rv.x = (unsigned)cnt | (c7[0] << 16);
        rv.y = c7[1] | (c7[2] << 16);
        rv.z = c7[3] | (c7[4] << 16);
        rv.w = c7[5] | (c7[6] << 16);
        g_row[row] = rv;
        #pragma unroll
        for (int k = 7; k < KC; ++k)
            if (k < cnt)
                g_sorted[(size_t)row * CSTRIDE + k] =
                    (unsigned short)(a[k] & 0xFFFFu);
    }
    __threadfence();   // release g_row/g_sorted before owner atomics

    // ========== phase C: eager-chain greedy matcher (leaders only) =========
    // owner[j] = min packed (row<<5|pos) ever proposed (atomicMin, monotone).
    // Packed lexicographic order == row priority. On displacement, the winner
    // continues the displaced row's walk (position from the returned value).
    // Fixed point is order-independent == sequential greedy (rounds 3-13).
    if (lead) {
        int cur = row, p = 0, ccnt = cnt;
        uint4 crv = rv;
        bool own = true;
        while (p < ccnt) {
            int j = cand_at(crv, p, cur, own);
            int my = (cur << 5) | p;
            int old = atomicMin(&g_owner[j], my);
            if (old < my) { ++p; continue; }     // better owner: advance
            if (old == OWNER_INIT) break;        // parked in empty slot: done
            cur = old >> 5;                      // continue displaced row
            p = (old & 31) + 1;
            crv = __ldcg(&g_row[cur]);
            ccnt = (int)(crv.x & 0xFFFFu);
            own = false;
        }
    }
    gsync(1);

    // ========== phase D: gt-side loss (owner[j]>>5 IS the matched row) =====
    // At fixed point each row owns <=1 gt, so iterating gts enumerates
    // exactly the matched pairs. Cleanup spread over all blocks.
    if (tid < ROWS_PB) {
        int c = b * ROWS_PB + tid;
        if (c < NCPAD) g_cellcnt[c] = 0;         // zero-state for next replay
    }

    float sc = 0.f, ss = 0.f, so = 0.f, si = 0.f, cf = 0.f;
    if (lead && row < n) {
        int v = __ldcg(&g_owner[row]);           // atomics live in L2
        if (v != OWNER_INIT) {
            int r = v >> 5;                      // matched pred row
            cf = 1.0f;
            const float* pp = pred + (size_t)r * 7;
            const float* gg = gt + (size_t)row * 7;
            float p0 = __ldg(pp),     p1 = __ldg(pp + 1), p2 = __ldg(pp + 2);
            float p3 = __ldg(pp + 3), p4 = __ldg(pp + 4), p5 = __ldg(pp + 5);
            float p6 = __ldg(pp + 6);
            float g0 = __ldg(gg),     g1 = __ldg(gg + 1), g2 = __ldg(gg + 2);
            float g3 = __ldg(gg + 3), g4 = __ldg(gg + 4), g5 = __ldg(gg + 5);
            float g6 = __ldg(gg + 6);
            sc = sl1(p0 - g0) + sl1(p1 - g1) + sl1(p2 - g2);
            ss = sl1(p3 - g3) + sl1(p4 - g4) + sl1(p5 - g5);
            float dth = p6 - g6;
            dth = fmaf(-rintf(dth * 0.15915494309f), 6.283185307f, dth);
            so = sl1(dth);                       // sl1(|.|) symmetric
            float iw = fminf(p0 + p3 * 0.5f, g0 + g3 * 0.5f)
                     - fmaxf(p0 - p3 * 0.5f, g0 - g3 * 0.5f);
            iw = fmaxf(iw, 0.0f);
            float ih = fminf(p1 + p4 * 0.5f, g1 + g4 * 0.5f)
                     - fmaxf(p1 - p4 * 0.5f, g1 - g4 * 0.5f);
            ih = fmaxf(ih, 0.0f);
            float inter = iw * ih;
            float uni = p3 * p4 + g3 * g4 - inter;
            si = 1.0f - inter / (uni + 1e-6f);
        }
    }
    #pragma unroll
    for (int o = 16; o; o >>= 1) {
        sc += __shfl_down_sync(0xFFFFFFFFu, sc, o);
        ss += __shfl_down_sync(0xFFFFFFFFu, ss, o);
        so += __shfl_down_sync(0xFFFFFFFFu, so, o);
        si += __shfl_down_sync(0xFFFFFFFFu, si, o);
        cf += __shfl_down_sync(0xFFFFFFFFu, cf, o);
    }
    if (lane == 0 && cf != 0.0f) {
        atomicAdd(&g_acc[0], sc);
        atomicAdd(&g_acc[1], ss);
        atomicAdd(&g_acc[2], so);
        atomicAdd(&g_acc[3], si);
        atomicAdd(&g_acc[4], cf);
    }

    // ========== finalize: arrive-only; last arriver writes out =============
    __syncthreads();
    if (tid == 0) {
        __threadfence();
        unsigned a = atomicAdd((unsigned*)&g_bcnt[2], 1u);
        if (a == GBLK - 1) {
            g_bcnt[2] = 0;
            float a0 = atomicAdd(&g_acc[0], 0.0f);
            float a1 = atomicAdd(&g_acc[1], 0.0f);
            float a2 = atomicAdd(&g_acc[2], 0.0f);
            float a3 = atomicAdd(&g_acc[3], 0.0f);
            float a4 = atomicAdd(&g_acc[4], 0.0f);
            float k  = fmaxf(a4, 1.0f);
            out[0] = a0 / (3.0f * k) + 0.5f * (a1 / (3.0f * k) + a2 / k)
                   + 2.0f * (a3 / k);
        }
    }
}

// ---------------- launch ----------------
extern "C" void kernel_launch(void* const* d_in, const int* in_sizes, int n_in,
                              void* d_out, int out_size) {
    const float* pred = (const float*)d_in[0];
    const float* gt   = (const float*)d_in[1];
    int m = in_sizes[0] / 7;
    int n = in_sizes[1] / 7;
    fused_kernel<<<GBLK, TBLK>>>(pred, gt, m, n, (float*)d_out);
}

// round 15
// speedup vs baseline: 1.2330x; 1.2330x over previous
#include <cuda_runtime.h>
#include <cstdint>

#define GRID1   20
#define NCPAD   8192
#define CAP     16             // bucket capacity (overflow P ~ 2e-12)
#define KC      20             // merged candidate cap (P(cnt>20) ~ 1e-9)
#define KC_L    12             // per-quad-thread local cap
#define STAGE   24             // per-row smem staging slots
#define CSTRIDE 32
#define MAXM    8192
#define MAXN    8192
#define GBLK    128
#define TBLK    256
#define GSZ     4              // threads per pred row (round-13 optimum)
#define ROWS_PB (TBLK / GSZ)   // 64 rows per block
#define OWNER_INIT 0x7FFFFFFF

typedef unsigned long long u64;

// ---------------- device scratch (no allocations allowed) ----------------
__device__ int            g_cellcnt[NCPAD];          // zero-init; phase D re-zeros
__device__ float4         g_bucket[NCPAD * CAP];     // (x,y,z,bitcast id)
__device__ uint4          g_row[MAXM];               // cnt | first 7 sorted candidates
__device__ unsigned short g_sorted[MAXM * CSTRIDE];  // overflow (pos >= 7)
__device__ int            g_owner[MAXN];             // packed (row<<5 | pos)
__device__ float          g_acc[5];
__device__ volatile unsigned g_bcnt[4];              // zero-init; self-resetting
__device__ volatile unsigned g_bgen[4];              // monotonic generation

__device__ __forceinline__ int cell1(float x) {
    int c = (int)floorf(x * 0.2f);
    return min(max(c, 0), GRID1 - 1);
}

// Generation-based grid barrier; all GBLK blocks co-resident (128 <= 148 SMs).
__device__ __forceinline__ void gsync(int k) {
    __syncthreads();
    if (threadIdx.x == 0) {
        unsigned old = g_bgen[k];
        __threadfence();
        unsigned a = atomicAdd((unsigned*)&g_bcnt[k], 1u);
        if (a == GBLK - 1) {
            g_bcnt[k] = 0;
            __threadfence();
            atomicAdd((unsigned*)&g_bgen[k], 1u);
        } else {
            while (g_bgen[k] == old) { }
        }
    }
    __syncthreads();
    __threadfence();
}

// candidate p of a row given its packed uint4; own=true may use L1 (own writes)
__device__ __forceinline__ int cand_at(uint4 rv, int p, int row, bool own) {
    if (p < 7) {
        unsigned w = (p == 0) ? rv.x : (p < 3) ? rv.y : (p < 5) ? rv.z : rv.w;
        int sh = (p == 0) ? 16 : ((p & 1) ? 0 : 16);
        return (int)((w >> sh) & 0xFFFFu);
    }
    const unsigned short* q = &g_sorted[(size_t)row * CSTRIDE + p];
    return own ? (int)*q : (int)__ldcg(q);
}

__device__ __forceinline__ float sl1(float x) {
    float a = fabsf(x);
    return (a < 1.0f) ? 0.5f * a * a : a - 0.5f;
}

__global__ void __launch_bounds__(TBLK)
fused_kernel(const float* __restrict__ pred, const float* __restrict__ gt,
             int m, int n, float* __restrict__ out) {
    __shared__ u64 s_keys[ROWS_PB * STAGE];     // 12 KB staging
    __shared__ int s_cnt[ROWS_PB];
    int b = blockIdx.x, tid = threadIdx.x;
    int lane = tid & 31;
    int gtid = b * TBLK + tid;
    int row  = gtid >> 2;                        // quad: 4 threads per pred row
    int q    = tid & (GSZ - 1);
    int lrow = tid >> 2;                         // row index within block
    bool rowv = (row < m);
    bool lead = (q == 0) && rowv;

    if (tid < ROWS_PB) s_cnt[tid] = 0;

    // All quad lanes load their row's pred xyz (same line; broadcast).
    float px = 0.f, py = 0.f, pz = 0.f;
    if (rowv) {
        px = __ldg(&pred[row * 7 + 0]);
        py = __ldg(&pred[row * 7 + 1]);
        pz = __ldg(&pred[row * 7 + 2]);
    }

    // ========== phase A: build + init, spread over ALL 128 blocks ==========
    if (b == 0 && tid >= ROWS_PB && tid < ROWS_PB + 5) g_acc[tid - ROWS_PB] = 0.0f;
    if (tid < ROWS_PB) {
        int r = b * ROWS_PB + tid;
        if (r < n) {
            g_owner[r] = OWNER_INIT;
            const float* g = gt + (size_t)r * 7;
            float gx = __ldg(g), gy = __ldg(g + 1), gz = __ldg(g + 2);
            int c = (cell1(gz) * GRID1 + cell1(gy)) * GRID1 + cell1(gx);
            int slot = atomicAdd(&g_cellcnt[c], 1);
            if (slot < CAP)
                g_bucket[c * CAP + slot] =
                    make_float4(gx, gy, gz, __int_as_float(r));
        }
    }
    gsync(0);

    // ========== phase B: quad-parallel query (round-13 optimum) ============
    // 27 neighbor cells split 7-per-quad-thread (k = q + 4t, k<27): union ==
    // full [cell1(px-5),cell1(px+5)]^3 superset (monotone f32 ops); exact
    // dsq<25 test -> identical candidate set to brute force (rounds 1-14).
    // Keys (fbits(dsq)<<32 | j) unique -> staging-order races erased by the
    // sorted merge; exact serial-argmin order.
    uint4 rv = make_uint4(0, 0, 0, 0);
    int   cnt = 0;
    if (rowv) {
        int x0 = cell1(px - 5.0f), x1 = cell1(px + 5.0f);
        int y0 = cell1(py - 5.0f), y1 = cell1(py + 5.0f);
        int z0 = cell1(pz - 5.0f), z1 = cell1(pz + 5.0f);

        u64 loc[KC_L];
        #pragma unroll
        for (int k = 0; k < KC_L; ++k) loc[k] = ~0ull;
        int lc = 0;

        int    cc[7], ci[7];
        float4 v0[7];
        #pragma unroll
        for (int t = 0; t < 7; ++t) {
            int k = q + GSZ * t;
            int zz = z0 + k / 9, yy = y0 + (k % 9) / 3, xx = x0 + k % 3;
            bool ok = (k < 27) && (zz <= z1) && (yy <= y1) && (xx <= x1);
            int c = (zz * GRID1 + yy) * GRID1 + xx;
            c = min(max(c, 0), NCPAD - 1);       // clamp: always in-bounds
            ci[t] = c;
            cc[t] = ok ? __ldg(&g_cellcnt[c]) : 0;
        }
        #pragma unroll
        for (int t = 0; t < 7; ++t) v0[t] = __ldg(&g_bucket[ci[t] * CAP]);

        #pragma unroll
        for (int t = 0; t < 7; ++t) {
            int c2 = min(cc[t], CAP);
            for (int e = 0; e < c2; ++e) {       // c2>1 rare (mean ~1)
                float4 v = (e == 0) ? v0[t] : __ldg(&g_bucket[ci[t] * CAP + e]);
                float dx = px - v.x, dy = py - v.y, dz = pz - v.z;
                float d = fmaf(dx, dx, fmaf(dy, dy, dz * dz));
                if (d < 25.0f) {
                    u64 key = ((u64)__float_as_uint(d) << 32)
                            | (unsigned)__float_as_int(v.w);
                    ++lc;
                    #pragma unroll
                    for (int k2 = 0; k2 < KC_L; ++k2) {   // register min-sweep
                        u64 mn = min(loc[k2], key);
                        key = loc[k2] ^ key ^ mn;
                        loc[k2] = mn;
                    }
                }
            }
        }
        lc = min(lc, KC_L);
        if (lc > 0) {
            int pos = atomicAdd(&s_cnt[lrow], lc);
            #pragma unroll
            for (int e = 0; e < KC_L; ++e)
                if (e < lc && pos + e < STAGE)
                    s_keys[lrow * STAGE + pos + e] = loc[e];
        }
    }
    __syncwarp(0xFFFFFFFFu);                     // quad is intra-warp

    if (lead) {
        int tot = min(s_cnt[lrow], STAGE);
        unsigned c7[7];
        if (tot <= 8) {
            // fast path (P ~ 97%): 8-register min-sweep merge
            u64 a8[8];
            #pragma unroll
            for (int k = 0; k < 8; ++k) a8[k] = ~0ull;
            for (int e = 0; e < tot; ++e) {
                u64 key = s_keys[lrow * STAGE + e];
                #pragma unroll
                for (int k2 = 0; k2 < 8; ++k2) {
                    u64 mn = min(a8[k2], key);
                    key = a8[k2] ^ key ^ mn;
                    a8[k2] = mn;
                }
            }
            cnt = tot;
            #pragma unroll
            for (int k = 0; k < 7; ++k)
                c7[k] = (k < cnt) ? (unsigned)(a8[k] & 0xFFFFu) : 0u;
            if (cnt == 8)
                g_sorted[(size_t)row * CSTRIDE + 7] =
                    (unsigned short)(a8[7] & 0xFFFFu);
        } else {
            // rare path: local-mem insertion sort (same ascending u64 order)
            u64 ls[STAGE];
            for (int e = 0; e < tot; ++e) ls[e] = s_keys[lrow * STAGE + e];
            for (int e = 1; e < tot; ++e) {
                u64 v = ls[e];
                int d = e;
                while (d > 0 && ls[d - 1] > v) { ls[d] = ls[d - 1]; --d; }
                ls[d] = v;
            }
            cnt = min(tot, KC);
            #pragma unroll
            for (int k = 0; k < 7; ++k)
                c7[k] = (k < cnt) ? (unsigned)(ls[k] & 0xFFFFu) : 0u;
            for (int k = 7; k < cnt; ++k)
                g_sorted[(size_t)row * CSTRIDE + k] =
                    (unsigned short)(ls[k] & 0xFFFFu);
        }
        rv.x = (unsigned)cnt | (c7[0] << 16);
        rv.y = c7[1] | (c7[2] << 16);
        rv.z = c7[3] | (c7[4] << 16);
        rv.w = c7[5] | (c7[6] << 16);
        g_row[row] = rv;
    }
    __threadfence();   // release g_row/g_sorted before owner atomics

    // ========== phase C: eager-chain greedy matcher (leaders only) =========
    // owner[j] = min packed (row<<5|pos) ever proposed (atomicMin, monotone).
    // Packed lexicographic order == row priority. On displacement, the winner
    // continues the displaced row's walk (position from the returned value).
    // Fixed point is order-independent == sequential greedy (rounds 3-14).
    if (lead) {
        int cur = row, p = 0, ccnt = cnt;
        uint4 crv = rv;
        bool own = true;
        while (p < ccnt) {
            int j = cand_at(crv, p, cur, own);
            int my = (cur << 5) | p;
            int old = atomicMin(&g_owner[j], my);
            if (old < my) { ++p; continue; }     // better owner: advance
            if (old == OWNER_INIT) break;        // parked in empty slot: done
            cur = old >> 5;                      // continue displaced row
            p = (old & 31) + 1;
            crv = __ldcg(&g_row[cur]);
            ccnt = (int)(crv.x & 0xFFFFu);
            own = false;
        }
    }
    gsync(1);

    // ========== phase D: gt-side loss (owner[j]>>5 IS the matched row) =====
    // At fixed point each row owns <=1 gt, so iterating gts (one per quad
    // leader, gt index == row) enumerates exactly the matched pairs.
    if (tid < ROWS_PB) {
        int c = b * ROWS_PB + tid;
        if (c < NCPAD) g_cellcnt[c] = 0;         // zero-state for next replay
    }

    float sc = 0.f, ss = 0.f, so = 0.f, si = 0.f, cf = 0.f;
    if (lead && row < n) {
        int v = __ldcg(&g_owner[row]);           // atomics live in L2
        if (v != OWNER_INIT) {
            int r = v >> 5;                      // matched pred row
            cf = 1.0f;
            const float* pp = pred + (size_t)r * 7;
            const float* gg = gt + (size_t)row * 7;
            float p0 = __ldg(pp),     p1 = __ldg(pp + 1), p2 = __ldg(pp + 2);
            float p3 = __ldg(pp + 3), p4 = __ldg(pp + 4), p5 = __ldg(pp + 5);
            float p6 = __ldg(pp + 6);
            float g0 = __ldg(gg),     g1 = __ldg(gg + 1), g2 = __ldg(gg + 2);
            float g3 = __ldg(gg + 3), g4 = __ldg(gg + 4), g5 = __ldg(gg + 5);
            float g6 = __ldg(gg + 6);
            sc = sl1(p0 - g0) + sl1(p1 - g1) + sl1(p2 - g2);
            ss = sl1(p3 - g3) + sl1(p4 - g4) + sl1(p5 - g5);
            float dth = p6 - g6;
            dth = fmaf(-rintf(dth * 0.15915494309f), 6.283185307f, dth);
            so = sl1(dth);                       // sl1(|.|) symmetric
            float iw = fminf(p0 + p3 * 0.5f, g0 + g3 * 0.5f)
                     - fmaxf(p0 - p3 * 0.5f, g0 - g3 * 0.5f);
            iw = fmaxf(iw, 0.0f);
            float ih = fminf(p1 + p4 * 0.5f, g1 + g4 * 0.5f)
                     - fmaxf(p1 - p4 * 0.5f, g1 - g4 * 0.5f);
            ih = fmaxf(ih, 0.0f);
            float inter = iw * ih;
            float uni = p3 * p4 + g3 * g4 - inter;
            si = 1.0f - inter / (uni + 1e-6f);
        }
    }
    #pragma unroll
    for (int o = 16; o; o >>= 1) {
        sc += __shfl_down_sync(0xFFFFFFFFu, sc, o);
        ss += __shfl_down_sync(0xFFFFFFFFu, ss, o);
        so += __shfl_down_sync(0xFFFFFFFFu, so, o);
        si += __shfl_down_sync(0xFFFFFFFFu, si, o);
        cf += __shfl_down_sync(0xFFFFFFFFu, cf, o);
    }
    if (lane == 0 && cf != 0.0f) {
        atomicAdd(&g_acc[0], sc);
        atomicAdd(&g_acc[1], ss);
        atomicAdd(&g_acc[2], so);
        atomicAdd(&g_acc[3], si);
        atomicAdd(&g_acc[4], cf);
    }

    // ========== finalize: arrive-only; last arriver writes out =============
    __syncthreads();
    if (tid == 0) {
        __threadfence();
        unsigned a = atomicAdd((unsigned*)&g_bcnt[2], 1u);
        if (a == GBLK - 1) {
            g_bcnt[2] = 0;
            float a0 = atomicAdd(&g_acc[0], 0.0f);
            float a1 = atomicAdd(&g_acc[1], 0.0f);
            float a2 = atomicAdd(&g_acc[2], 0.0f);
            float a3 = atomicAdd(&g_acc[3], 0.0f);
            float a4 = atomicAdd(&g_acc[4], 0.0f);
            float k  = fmaxf(a4, 1.0f);
            out[0] = a0 / (3.0f * k) + 0.5f * (a1 / (3.0f * k) + a2 / k)
                   + 2.0f * (a3 / k);
        }
    }
}

// ---------------- launch ----------------
extern "C" void kernel_launch(void* const* d_in, const int* in_sizes, int n_in,
                              void* d_out, int out_size) {
    const float* pred = (const float*)d_in[0];
    const float* gt   = (const float*)d_in[1];
    int m = in_sizes[0] / 7;
    int n = in_sizes[1] / 7;
    fused_kernel<<<GBLK, TBLK>>>(pred, gt, m, n, (float*)d_out);
}

// round 16
// speedup vs baseline: 1.2420x; 1.0073x over previous
#include <cuda_runtime.h>
#include <cstdint>

#define GRID1   20
#define NCPAD   8192
#define CAP     16             // bucket capacity (overflow P ~ 2e-12)
#define KC      20             // merged candidate cap (P(cnt>20) ~ 1e-9)
#define KC_L    12             // per-quad-thread local cap
#define STAGE   24             // per-row smem staging slots
#define CSTRIDE 32
#define MAXM    8192
#define MAXN    8192
#define GBLK    128
#define TBLK    256
#define GSZ     4              // threads per pred row (round-13/15 optimum)
#define ROWS_PB (TBLK / GSZ)   // 64 rows per block

typedef unsigned long long u64;
#define OWNER_INIT (~0ull)

// ---------------- device scratch (no allocations allowed) ----------------
__device__ int            g_cellcnt[NCPAD];          // zero-init; finalize re-zeros
__device__ float4         g_bucket[NCPAD * CAP];     // (x,y,z,bitcast id)
__device__ uint4          g_row[MAXM];               // cnt | first 7 sorted candidates
__device__ unsigned short g_sorted[MAXM * CSTRIDE];  // overflow (pos >= 7)
__device__ u64            g_owner[MAXN];             // ((row<<5|pos)<<32) | fbits(L)
__device__ float          g_accN;                    // loss numerator (telescoped)
__device__ float          g_accK;                    // match count
__device__ volatile unsigned g_bcnt[4];              // zero-init; self-resetting
__device__ volatile unsigned g_bgen[4];              // monotonic generation

__device__ __forceinline__ int cell1(float x) {
    int c = (int)floorf(x * 0.2f);
    return min(max(c, 0), GRID1 - 1);
}

// Generation-based grid barrier; all GBLK blocks co-resident (128 <= 148 SMs).
__device__ __forceinline__ void gsync(int k) {
    __syncthreads();
    if (threadIdx.x == 0) {
        unsigned old = g_bgen[k];
        __threadfence();
        unsigned a = atomicAdd((unsigned*)&g_bcnt[k], 1u);
        if (a == GBLK - 1) {
            g_bcnt[k] = 0;
            __threadfence();
            atomicAdd((unsigned*)&g_bgen[k], 1u);
        } else {
            while (g_bgen[k] == old) { }
        }
    }
    __syncthreads();
    __threadfence();
}

// candidate p of a row given its packed uint4; own=true may use L1 (own writes)
__device__ __forceinline__ int cand_at(uint4 rv, int p, int row, bool own) {
    if (p < 7) {
        unsigned w = (p == 0) ? rv.x : (p < 3) ? rv.y : (p < 5) ? rv.z : rv.w;
        int sh = (p == 0) ? 16 : ((p & 1) ? 0 : 16);
        return (int)((w >> sh) & 0xFFFFu);
    }
    const unsigned short* q = &g_sorted[(size_t)row * CSTRIDE + p];
    return own ? (int)*q : (int)__ldcg(q);
}

__device__ __forceinline__ float sl1(float x) {
    float a = fabsf(x);
    return (a < 1.0f) ? 0.5f * a * a : a - 0.5f;
}

// Per-pair loss numerator from register-resident rows.
__device__ __forceinline__ float pair_numer(const float* P, const float* G) {
    float sc = sl1(P[0] - G[0]) + sl1(P[1] - G[1]) + sl1(P[2] - G[2]);
    float ss = sl1(P[3] - G[3]) + sl1(P[4] - G[4]) + sl1(P[5] - G[5]);
    float dth = P[6] - G[6];
    dth = fmaf(-rintf(dth * 0.15915494309f), 6.283185307f, dth);
    float so = sl1(dth);                 // sl1(|.|) symmetric: wrap dir irrelevant
    float iw = fminf(P[0] + P[3] * 0.5f, G[0] + G[3] * 0.5f)
             - fmaxf(P[0] - P[3] * 0.5f, G[0] - G[3] * 0.5f);
    iw = fmaxf(iw, 0.0f);
    float ih = fminf(P[1] + P[4] * 0.5f, G[1] + G[4] * 0.5f)
             - fmaxf(P[1] - P[4] * 0.5f, G[1] - G[4] * 0.5f);
    ih = fmaxf(ih, 0.0f);
    float inter = iw * ih;
    float uni = P[3] * P[4] + G[3] * G[4] - inter;
    float si = 1.0f - inter / (uni + 1e-6f);
    return sc * (1.0f / 3.0f) + 0.5f * (ss * (1.0f / 3.0f) + so) + 2.0f * si;
}

__global__ void __launch_bounds__(TBLK)
fused_kernel(const float* __restrict__ pred, const float* __restrict__ gt,
             int m, int n, float* __restrict__ out) {
    __shared__ u64 s_keys[ROWS_PB * STAGE];     // 12 KB staging
    __shared__ int s_cnt[ROWS_PB];
    int b = blockIdx.x, tid = threadIdx.x;
    int gtid = b * TBLK + tid;
    int row  = gtid >> 2;                        // quad: 4 threads per pred row
    int q    = tid & (GSZ - 1);
    int lrow = tid >> 2;                         // row index within block
    bool rowv = (row < m);
    bool lead = (q == 0) && rowv;

    if (tid < ROWS_PB) s_cnt[tid] = 0;

    // All quad lanes load their row's pred xyz (same line; broadcast).
    float px = 0.f, py = 0.f, pz = 0.f;
    if (rowv) {
        px = __ldg(&pred[row * 7 + 0]);
        py = __ldg(&pred[row * 7 + 1]);
        pz = __ldg(&pred[row * 7 + 2]);
    }

    // ========== phase A: build + init, spread over ALL 128 blocks ==========
    if (b == 0 && tid == ROWS_PB)     g_accN = 0.0f;
    if (b == 0 && tid == ROWS_PB + 1) g_accK = 0.0f;
    if (tid < ROWS_PB) {
        int r = b * ROWS_PB + tid;
        if (r < n) {
            g_owner[r] = OWNER_INIT;
            const float* g = gt + (size_t)r * 7;
            float gx = __ldg(g), gy = __ldg(g + 1), gz = __ldg(g + 2);
            int c = (cell1(gz) * GRID1 + cell1(gy)) * GRID1 + cell1(gx);
            int slot = atomicAdd(&g_cellcnt[c], 1);
            if (slot < CAP)
                g_bucket[c * CAP + slot] =
                    make_float4(gx, gy, gz, __int_as_float(r));
        }
    }
    gsync(0);

    // ========== phase B: quad-parallel query (round-15 champion) ===========
    // 27 neighbor cells split 7-per-quad-thread (k = q + 4t, k<27): union ==
    // full [cell1(px-5),cell1(px+5)]^3 superset (monotone f32 ops); exact
    // dsq<25 test -> identical candidate set to brute force (rounds 1-15).
    // Keys (fbits(dsq)<<32 | j) unique -> staging-order races erased by the
    // sorted merge; exact serial-argmin order.
    uint4 rv = make_uint4(0, 0, 0, 0);
    int   cnt = 0;
    if (rowv) {
        int x0 = cell1(px - 5.0f), x1 = cell1(px + 5.0f);
        int y0 = cell1(py - 5.0f), y1 = cell1(py + 5.0f);
        int z0 = cell1(pz - 5.0f), z1 = cell1(pz + 5.0f);

        u64 loc[KC_L];
        #pragma unroll
        for (int k = 0; k < KC_L; ++k) loc[k] = ~0ull;
        int lc = 0;

        int    cc[7], ci[7];
        float4 v0[7];
        #pragma unroll
        for (int t = 0; t < 7; ++t) {
            int k = q + GSZ * t;
            int zz = z0 + k / 9, yy = y0 + (k % 9) / 3, xx = x0 + k % 3;
            bool ok = (k < 27) && (zz <= z1) && (yy <= y1) && (xx <= x1);
            int c = (zz * GRID1 + yy) * GRID1 + xx;
            c = min(max(c, 0), NCPAD - 1);       // clamp: always in-bounds
            ci[t] = c;
            cc[t] = ok ? __ldg(&g_cellcnt[c]) : 0;
        }
        #pragma unroll
        for (int t = 0; t < 7; ++t) v0[t] = __ldg(&g_bucket[ci[t] * CAP]);

        #pragma unroll
        for (int t = 0; t < 7; ++t) {
            int c2 = min(cc[t], CAP);
            for (int e = 0; e < c2; ++e) {       // c2>1 rare (mean ~1)
                float4 v = (e == 0) ? v0[t] : __ldg(&g_bucket[ci[t] * CAP + e]);
                float dx = px - v.x, dy = py - v.y, dz = pz - v.z;
                float d = fmaf(dx, dx, fmaf(dy, dy, dz * dz));
                if (d < 25.0f) {
                    u64 key = ((u64)__float_as_uint(d) << 32)
                            | (unsigned)__float_as_int(v.w);
                    ++lc;
                    #pragma unroll
                    for (int k2 = 0; k2 < KC_L; ++k2) {   // register min-sweep
                        u64 mn = min(loc[k2], key);
                        key = loc[k2] ^ key ^ mn;
                        loc[k2] = mn;
                    }
                }
            }
        }
        lc = min(lc, KC_L);
        if (lc > 0) {
            int pos = atomicAdd(&s_cnt[lrow], lc);
            #pragma unroll
            for (int e = 0; e < KC_L; ++e)
                if (e < lc && pos + e < STAGE)
                    s_keys[lrow * STAGE + pos + e] = loc[e];
        }
    }
    __syncwarp(0xFFFFFFFFu);                     // quad is intra-warp

    if (lead) {
        int tot = min(s_cnt[lrow], STAGE);
        unsigned c7[7];
        if (tot <= 8) {
            // fast path (P ~ 97%): 8-register min-sweep merge
            u64 a8[8];
            #pragma unroll
            for (int k = 0; k < 8; ++k) a8[k] = ~0ull;
            for (int e = 0; e < tot; ++e) {
                u64 key = s_keys[lrow * STAGE + e];
                #pragma unroll
                for (int k2 = 0; k2 < 8; ++k2) {
                    u64 mn = min(a8[k2], key);
                    key = a8[k2] ^ key ^ mn;
                    a8[k2] = mn;
                }
            }
            cnt = tot;
            #pragma unroll
            for (int k = 0; k < 7; ++k)
                c7[k] = (k < cnt) ? (unsigned)(a8[k] & 0xFFFFu) : 0u;
            if (cnt == 8)
                g_sorted[(size_t)row * CSTRIDE + 7] =
                    (unsigned short)(a8[7] & 0xFFFFu);
        } else {
            // rare path: local-mem insertion sort (same ascending u64 order)
            u64 ls[STAGE];
            for (int e = 0; e < tot; ++e) ls[e] = s_keys[lrow * STAGE + e];
            for (int e = 1; e < tot; ++e) {
                u64 v = ls[e];
                int d = e;
                while (d > 0 && ls[d - 1] > v) { ls[d] = ls[d - 1]; --d; }
                ls[d] = v;
            }
            cnt = min(tot, KC);
            #pragma unroll
            for (int k = 0; k < 7; ++k)
                c7[k] = (k < cnt) ? (unsigned)(ls[k] & 0xFFFFu) : 0u;
            for (int k = 7; k < cnt; ++k)
                g_sorted[(size_t)row * CSTRIDE + k] =
                    (unsigned short)(ls[k] & 0xFFFFu);
        }
        rv.x = (unsigned)cnt | (c7[0] << 16);
        rv.y = c7[1] | (c7[2] << 16);
        rv.z = c7[3] | (c7[4] << 16);
        rv.w = c7[5] | (c7[6] << 16);
        g_row[row] = rv;
    }
    __threadfence();   // release g_row/g_sorted before owner atomics

    // ========== phase C: eager-chain matcher + telescoped loss =============
    // owner64[j] = min over proposals of ((row<<5|pos)<<32 | fbits(L_pair)).
    // High 32 bits are the verified packed priority (unique per proposal), so
    // atomicMin ordering is IDENTICAL to rounds 8-15; the pair loss rides in
    // the low bits. Accounting per linearized owner transition:
    //   INIT -> v          : accN += L_new, accK += 1
    //   v_old -> v_new     : accN += L_new - L_old (L_old read from the word,
    //                        no recomputation) and the displaced row's walk
    //                        continues. Sum telescopes exactly to the fixed
    //                        point == sequential greedy matches.
    // Pre-claim peek (issued in the same wave as the gt-row loads) skips
    // positions whose owner is already smaller: current <= stale < mine,
    // permanently safe (monotonicity; round-10-proven rule).
    if (lead) {
        int cur = row, p = 0, ccnt = cnt;
        uint4 crv = rv;
        bool own = true;
        float P[7];
        #pragma unroll
        for (int k = 0; k < 7; ++k) P[k] = __ldg(&pred[(size_t)row * 7 + k]);

        while (p < ccnt) {
            int j = cand_at(crv, p, cur, own);
            u64 myhi = (u64)((unsigned)((cur << 5) | p));
            // one wave: peek + full gt row (independent loads)
            u64 peek = __ldcg(&g_owner[j]);
            float G[7];
            #pragma unroll
            for (int k = 0; k < 7; ++k) G[k] = __ldg(&gt[(size_t)j * 7 + k]);
            if ((peek >> 32) < myhi) { ++p; continue; }   // hopeless: skip
            float L = pair_numer(P, G);
            u64 my = (myhi << 32) | (u64)__float_as_uint(L);
            u64 old = atomicMin(&g_owner[j], my);
            if (old < my) { ++p; continue; }              // lost race: advance
            if (old == OWNER_INIT) {                      // claimed empty slot
                atomicAdd(&g_accN, L);
                atomicAdd(&g_accK, 1.0f);
                break;
            }
            // displaced previous owner: swap contribution, continue its walk
            float Lold = __uint_as_float((unsigned)(old & 0xFFFFFFFFull));
            atomicAdd(&g_accN, L - Lold);
            cur = (int)(old >> 37);
            p = (int)((old >> 32) & 31u) + 1;
            crv = __ldcg(&g_row[cur]);
            ccnt = (int)(crv.x & 0xFFFFu);
            own = false;
            #pragma unroll
            for (int k = 0; k < 7; ++k)
                P[k] = __ldg(&pred[(size_t)cur * 7 + k]);
        }
    }

    // ========== finalize: arrive-only; last block writes out + cleanup =====
    __syncthreads();
    __shared__ int s_last;
    if (tid == 0) {
        __threadfence();                 // order this block's REDs
        unsigned a = atomicAdd((unsigned*)&g_bcnt[2], 1u);
        s_last = (a == GBLK - 1) ? 1 : 0;
        if (s_last) g_bcnt[2] = 0;
    }
    __syncthreads();
    if (s_last) {
        if (tid == 0) {
            float N = atomicAdd(&g_accN, 0.0f);
            float K = atomicAdd(&g_accK, 0.0f);
            out[0] = N / fmaxf(K, 1.0f);
        }
        for (int c = tid; c < NCPAD; c += TBLK)   // zero-state for next replay
            g_cellcnt[c] = 0;
    }
}

// ---------------- launch ----------------
extern "C" void kernel_launch(void* const* d_in, const int* in_sizes, int n_in,
                              void* d_out, int out_size) {
    const float* pred = (const float*)d_in[0];
    const float* gt   = (const float*)d_in[1];
    int m = in_sizes[0] / 7;
    int n = in_sizes[1] / 7;
    fused_kernel<<<GBLK, TBLK>>>(pred, gt, m, n, (float*)d_out);
}